// round 3
// baseline (speedup 1.0000x reference)
#include <cuda_runtime.h>
#include <cuda_bf16.h>

// Problem constants (fixed by the reference setup_inputs)
#define BATCH   16
#define HW      512
#define MCOMP   200000
#define NBLK    64
#define NTHR    256
#define TOTAL_BLOCKS (BATCH * NBLK)

#define EPS_F   1e-10f
#define THR_F   1.1f            // 1.0 + DELTA

// Scratch: per-block partial sums (sum_w, sum_w*mismatch) + completion counter
__device__ float2 g_part[TOTAL_BLOCKS];
__device__ unsigned int g_count;   // zero-init; reset by last block each run

__device__ __forceinline__ void whdr_eval(float x1f, float y1f, float x2f, float y2f,
                                          float darkerf, float w,
                                          const float* __restrict__ img,
                                          float& ws, float& wm)
{
    const int x1 = (int)x1f, y1 = (int)y1f;
    const int x2 = (int)x2f, y2 = (int)y2f;
    const int darker = (int)darkerf;

    const float r1 = __ldg(img + y1 * HW + x1);
    const float r2 = __ldg(img + y2 * HW + x2);

    // alg = 1 if r2/(r1+eps) > thr ; 2 if r1/(r2+eps) > thr ; else 0
    int alg = 0;
    if (r2 > THR_F * (r1 + EPS_F))      alg = 1;
    else if (r1 > THR_F * (r2 + EPS_F)) alg = 2;

    ws += w;
    if (alg != darker) wm += w;
}

// Process record pair (2p, 2p+1): three 16B streaming loads
__device__ __forceinline__ void whdr_pair(const float4* __restrict__ c4, int p,
                                          const float* __restrict__ img,
                                          float& ws, float& wm)
{
    const float4 q0 = __ldcs(c4 + p * 3 + 0);
    const float4 q1 = __ldcs(c4 + p * 3 + 1);
    const float4 q2 = __ldcs(c4 + p * 3 + 2);
    // record A: x1,y1,x2,y2,darker,weight = q0.xyzw, q1.x, q1.y
    whdr_eval(q0.x, q0.y, q0.z, q0.w, q1.x, q1.y, img, ws, wm);
    // record B: q1.z, q1.w, q2.xyzw
    whdr_eval(q1.z, q1.w, q2.x, q2.y, q2.z, q2.w, img, ws, wm);
}

__global__ __launch_bounds__(NTHR)
void whdr_fused_kernel(const float* __restrict__ v_input,
                       const float* __restrict__ comparisons,
                       const int*   __restrict__ numComparisons,
                       float* __restrict__ out)
{
    const int b   = blockIdx.y;
    const int blk = blockIdx.x;
    const float* __restrict__ img = v_input + (size_t)b * HW * HW;
    const float* __restrict__ cb  = comparisons + (size_t)b * MCOMP * 6;
    const float4* __restrict__ c4 = (const float4*)cb;
    const int n      = numComparisons[b];
    const int npairs = n >> 1;

    float ws0 = 0.0f, wm0 = 0.0f;
    float ws1 = 0.0f, wm1 = 0.0f;

    const int stride = NBLK * NTHR;
    int p = blk * NTHR + threadIdx.x;
    // 2-way unrolled grid-stride over pairs: 8 independent image gathers in flight
    for (; p + stride < npairs; p += 2 * stride) {
        whdr_pair(c4, p,          img, ws0, wm0);
        whdr_pair(c4, p + stride, img, ws1, wm1);
    }
    if (p < npairs) whdr_pair(c4, p, img, ws0, wm0);

    // odd leftover record handled once per batch
    if (blk == 0 && threadIdx.x == 0 && (n & 1)) {
        const int m = n - 1;
        const float2* c2 = (const float2*)cb;
        const float2 a0 = __ldcs(c2 + m * 3 + 0);
        const float2 a1 = __ldcs(c2 + m * 3 + 1);
        const float2 a2 = __ldcs(c2 + m * 3 + 2);
        whdr_eval(a0.x, a0.y, a1.x, a1.y, a2.x, a2.y, img, ws0, wm0);
    }

    float ws = ws0 + ws1;
    float wm = wm0 + wm1;

    // block reduction (8 warps)
    __shared__ float s_ws[NTHR / 32];
    __shared__ float s_wm[NTHR / 32];
    const int lane = threadIdx.x & 31;
    const int warp = threadIdx.x >> 5;
    #pragma unroll
    for (int o = 16; o > 0; o >>= 1) {
        ws += __shfl_down_sync(0xFFFFFFFFu, ws, o);
        wm += __shfl_down_sync(0xFFFFFFFFu, wm, o);
    }
    if (lane == 0) { s_ws[warp] = ws; s_wm[warp] = wm; }
    __syncthreads();

    __shared__ bool s_last;
    if (warp == 0) {
        ws = (lane < NTHR / 32) ? s_ws[lane] : 0.0f;
        wm = (lane < NTHR / 32) ? s_wm[lane] : 0.0f;
        #pragma unroll
        for (int o = 4; o > 0; o >>= 1) {
            ws += __shfl_down_sync(0xFFFFFFFFu, ws, o);
            wm += __shfl_down_sync(0xFFFFFFFFu, wm, o);
        }
        if (lane == 0) {
            g_part[b * NBLK + blk] = make_float2(ws, wm);
            __threadfence();
            unsigned int prev = atomicAdd(&g_count, 1u);
            s_last = (prev == TOTAL_BLOCKS - 1);
        }
    }
    __syncthreads();

    // Last block performs the deterministic final reduction
    if (s_last) {
        __threadfence();  // acquire: make all g_part writes visible
        __shared__ float s_per[BATCH];
        // 8 warps, each handles 2 batches (64 partials per batch)
        const volatile float2* vp = (const volatile float2*)g_part;
        #pragma unroll
        for (int t = 0; t < 2; t++) {
            const int bb = warp * 2 + t;
            float fws = vp[bb * NBLK + lane].x + vp[bb * NBLK + 32 + lane].x;
            float fwm = vp[bb * NBLK + lane].y + vp[bb * NBLK + 32 + lane].y;
            #pragma unroll
            for (int o = 16; o > 0; o >>= 1) {
                fws += __shfl_down_sync(0xFFFFFFFFu, fws, o);
                fwm += __shfl_down_sync(0xFFFFFFFFu, fwm, o);
            }
            if (lane == 0) s_per[bb] = fwm / fws;
        }
        __syncthreads();
        if (threadIdx.x == 0) {
            float s = 0.0f;
            #pragma unroll
            for (int i = 0; i < BATCH; i++) s += s_per[i];
            out[0] = s * (1.0f / BATCH);
            g_count = 0;   // self-reset for next graph replay
        }
    }
}

extern "C" void kernel_launch(void* const* d_in, const int* in_sizes, int n_in,
                              void* d_out, int out_size)
{
    const float* v_input        = (const float*)d_in[0];
    const float* comparisons    = (const float*)d_in[1];
    const int*   numComparisons = (const int*)  d_in[2];
    float* out = (float*)d_out;

    dim3 grid(NBLK, BATCH, 1);
    whdr_fused_kernel<<<grid, NTHR>>>(v_input, comparisons, numComparisons, out);
}